// round 6
// baseline (speedup 1.0000x reference)
#include <cuda_runtime.h>

// Problem constants (fixed shapes from reference setup_inputs)
#define BB      4
#define NPTS    8192
#define SQ      2048
#define CF      64
#define NSAMPLE 32
#define CH_OUT  67      // 3 (xyz) + 64 (features)
#define RADIUS2 0.04f   // 0.2^2

// Scratch: features transposed to [B][N][C] so per-neighbor channel reads are contiguous.
__device__ float g_featT[(size_t)BB * NPTS * CF];

// ---------------------------------------------------------------------------
// Kernel 1: transpose features (B, C, N) -> (B, N, C)
// ---------------------------------------------------------------------------
__global__ void __launch_bounds__(256) transpose_feat_kernel(const float* __restrict__ feat) {
    __shared__ float tile[32][33];
    const int b  = blockIdx.z;
    const int n0 = blockIdx.x * 32;
    const int c0 = blockIdx.y * 32;
    const float* f  = feat    + (size_t)b * CF * NPTS;
    float*       ft = g_featT + (size_t)b * NPTS * CF;

#pragma unroll
    for (int i = 0; i < 4; i++) {
        int c = c0 + threadIdx.y + i * 8;
        int n = n0 + threadIdx.x;
        tile[threadIdx.y + i * 8][threadIdx.x] = f[(size_t)c * NPTS + n];
    }
    __syncthreads();
#pragma unroll
    for (int i = 0; i < 4; i++) {
        int n = n0 + threadIdx.y + i * 8;
        int c = c0 + threadIdx.x;
        ft[(size_t)n * CF + c] = tile[threadIdx.x][threadIdx.y + i * 8];
    }
}

// Exact reference arithmetic: d2 = (q2 + p2) - 2*qp, plain fp32 ops, no FMA.
__device__ __forceinline__ bool in_ball(float x, float y, float z,
                                        float qx, float qy, float qz, float q2) {
    const float p2 = __fadd_rn(__fadd_rn(__fmul_rn(x, x), __fmul_rn(y, y)),
                               __fmul_rn(z, z));
    const float qp = __fadd_rn(__fadd_rn(__fmul_rn(x, qx), __fmul_rn(y, qy)),
                               __fmul_rn(z, qz));
    const float d2 = __fsub_rn(__fadd_rn(q2, p2), __fmul_rn(2.0f, qp));
    return d2 < RADIUS2;
}

// ---------------------------------------------------------------------------
// Kernel 2: ball query + group. One warp per query point (b, s).
// Scan: 128 points / iteration (4 per lane, 3 float4 loads), software-pipelined
// prefetch of the next chunk to hide L2 latency. Early exit at 32 found.
// Gather: lane k loads its neighbor's 64 channels as 16 contiguous float4s
// (registers), stores coalesced with k innermost. No smem tile.
// ---------------------------------------------------------------------------
#define WARPS_PER_BLOCK 4

__global__ void __launch_bounds__(128) qag_kernel(const float* __restrict__ xyz,
                                                  const float* __restrict__ new_xyz,
                                                  float* __restrict__ out) {
    __shared__ int sidx[WARPS_PER_BLOCK][NSAMPLE];

    const int warp = threadIdx.x >> 5;
    const int lane = threadIdx.x & 31;
    const int q    = blockIdx.x * WARPS_PER_BLOCK + warp;   // global query id
    const int b    = q / SQ;
    const int s    = q % SQ;

    const float* nq = new_xyz + ((size_t)b * SQ + s) * 3;
    const float qx = nq[0], qy = nq[1], qz = nq[2];
    const float q2 = __fadd_rn(__fadd_rn(__fmul_rn(qx, qx), __fmul_rn(qy, qy)),
                               __fmul_rn(qz, qz));

    const float* px = xyz + (size_t)b * NPTS * 3;
    const float4* v = (const float4*)px;

    // ---------------- ball query: pipelined scan, early exit -----------------
    int cnt = 0;
    const unsigned full  = 0xffffffffu;
    const unsigned below = (1u << lane) - 1u;

    // Preload chunk 0 (each lane: 4 points = 3 contiguous float4s).
    float4 A  = v[3 * lane + 0];
    float4 Bv = v[3 * lane + 1];
    float4 Cv = v[3 * lane + 2];

    for (int base = 0; base < NPTS; base += 128) {
        // Prefetch next chunk (wraps to 0 on the last iter; harmless).
        const int nb = (base + 128) & (NPTS - 1);
        const float4* nv = (const float4*)(px + (size_t)nb * 3);
        const float4 nA = nv[3 * lane + 0];
        const float4 nB = nv[3 * lane + 1];
        const float4 nC = nv[3 * lane + 2];

        // points: P0=(A.x,A.y,A.z) P1=(A.w,Bv.x,Bv.y) P2=(Bv.z,Bv.w,Cv.x) P3=(Cv.y,Cv.z,Cv.w)
        unsigned m4 = 0;
        m4 |= (unsigned)in_ball(A.x,  A.y,  A.z,  qx, qy, qz, q2) << 0;
        m4 |= (unsigned)in_ball(A.w,  Bv.x, Bv.y, qx, qy, qz, q2) << 1;
        m4 |= (unsigned)in_ball(Bv.z, Bv.w, Cv.x, qx, qy, qz, q2) << 2;
        m4 |= (unsigned)in_ball(Cv.y, Cv.z, Cv.w, qx, qy, qz, q2) << 3;

        const unsigned b0 = __ballot_sync(full, m4 & 1u);
        const unsigned b1 = __ballot_sync(full, m4 & 2u);
        const unsigned b2 = __ballot_sync(full, m4 & 4u);
        const unsigned b3 = __ballot_sync(full, m4 & 8u);

        if (m4) {
            // in-ball points of lower lanes all have smaller point index
            const int pre = __popc(b0 & below) + __popc(b1 & below)
                          + __popc(b2 & below) + __popc(b3 & below);
#pragma unroll
            for (int j = 0; j < 4; j++) {
                if ((m4 >> j) & 1u) {
                    const int slot = cnt + pre + __popc(m4 & ((1u << j) - 1u));
                    if (slot < NSAMPLE) sidx[warp][slot] = base + 4 * lane + j;
                }
            }
        }
        cnt += __popc(b0) + __popc(b1) + __popc(b2) + __popc(b3);  // warp-uniform
        if (cnt >= NSAMPLE) break;                                 // uniform branch

        A = nA; Bv = nB; Cv = nC;
    }
    __syncwarp();

    // Pad with first index; all-zeros if no neighbor at all (matches reference).
    int myidx;
    if (cnt == 0) {
        myidx = 0;
    } else {
        const int c = cnt < NSAMPLE ? cnt : NSAMPLE;
        myidx = sidx[warp][lane < c ? lane : 0];
    }

    // ---------------- grouped_xyz: lane k handles neighbor k -----------------
    const size_t chs = (size_t)SQ * NSAMPLE;
    {
        const float x = px[myidx * 3 + 0];
        const float y = px[myidx * 3 + 1];
        const float z = px[myidx * 3 + 2];
        const size_t obase = ((size_t)b * CH_OUT) * chs + (size_t)s * NSAMPLE + lane;
        out[obase + 0 * chs] = x - qx;
        out[obase + 1 * chs] = y - qy;
        out[obase + 2 * chs] = z - qz;
    }

    // ---------------- grouped features: register gather, coalesced stores ----
    // Lane k reads neighbor k's 64 channels as 16 contiguous float4s (all
    // sectors fully used), then stores with k innermost (fully coalesced).
    {
        const float4* frow = (const float4*)(g_featT + ((size_t)b * NPTS + myidx) * CF);
        const size_t fbase = ((size_t)b * CH_OUT + 3) * chs + (size_t)s * NSAMPLE + lane;
#pragma unroll
        for (int chunk = 0; chunk < 4; chunk++) {
            const float4 v0 = frow[chunk * 4 + 0];
            const float4 v1 = frow[chunk * 4 + 1];
            const float4 v2 = frow[chunk * 4 + 2];
            const float4 v3 = frow[chunk * 4 + 3];
            float* o = out + fbase + (size_t)(chunk * 16) * chs;
            o[0 * chs]  = v0.x;  o[1 * chs]  = v0.y;  o[2 * chs]  = v0.z;  o[3 * chs]  = v0.w;
            o[4 * chs]  = v1.x;  o[5 * chs]  = v1.y;  o[6 * chs]  = v1.z;  o[7 * chs]  = v1.w;
            o[8 * chs]  = v2.x;  o[9 * chs]  = v2.y;  o[10 * chs] = v2.z;  o[11 * chs] = v2.w;
            o[12 * chs] = v3.x;  o[13 * chs] = v3.y;  o[14 * chs] = v3.z;  o[15 * chs] = v3.w;
        }
    }
}

// ---------------------------------------------------------------------------
// Launch
// ---------------------------------------------------------------------------
extern "C" void kernel_launch(void* const* d_in, const int* in_sizes, int n_in,
                              void* d_out, int out_size) {
    const float* xyz      = (const float*)d_in[0];  // (B, N, 3)
    const float* new_xyz  = (const float*)d_in[1];  // (B, S, 3)
    const float* features = (const float*)d_in[2];  // (B, C, N)
    float*       out      = (float*)d_out;          // (B, 67, S, 32)

    (void)in_sizes; (void)n_in; (void)out_size;

    dim3 tgrid(NPTS / 32, CF / 32, BB);
    dim3 tblock(32, 8);
    transpose_feat_kernel<<<tgrid, tblock>>>(features);

    const int nquery = BB * SQ;                       // 8192
    const int blocks = nquery / WARPS_PER_BLOCK;      // 2048
    qag_kernel<<<blocks, WARPS_PER_BLOCK * 32>>>(xyz, new_xyz, out);
}

// round 8
// speedup vs baseline: 1.4866x; 1.4866x over previous
#include <cuda_runtime.h>

// Problem constants (fixed shapes from reference setup_inputs)
#define BB      4
#define NPTS    8192
#define SQ      2048
#define CF      64
#define NSAMPLE 32
#define CH_OUT  67      // 3 (xyz) + 64 (features)
#define RADIUS2 0.04f   // 0.2^2

// Scratch: features transposed to [B][N][C] so per-neighbor channel reads are contiguous.
__device__ float g_featT[(size_t)BB * NPTS * CF];

// ---------------------------------------------------------------------------
// Kernel 1: transpose features (B, C, N) -> (B, N, C)
// ---------------------------------------------------------------------------
__global__ void __launch_bounds__(256) transpose_feat_kernel(const float* __restrict__ feat) {
    __shared__ float tile[32][33];
    const int b  = blockIdx.z;
    const int n0 = blockIdx.x * 32;
    const int c0 = blockIdx.y * 32;
    const float* f  = feat    + (size_t)b * CF * NPTS;
    float*       ft = g_featT + (size_t)b * NPTS * CF;

#pragma unroll
    for (int i = 0; i < 4; i++) {
        int c = c0 + threadIdx.y + i * 8;
        int n = n0 + threadIdx.x;
        tile[threadIdx.y + i * 8][threadIdx.x] = f[(size_t)c * NPTS + n];
    }
    __syncthreads();
#pragma unroll
    for (int i = 0; i < 4; i++) {
        int n = n0 + threadIdx.y + i * 8;
        int c = c0 + threadIdx.x;
        ft[(size_t)n * CF + c] = tile[threadIdx.x][threadIdx.y + i * 8];
    }
}

// Exact reference arithmetic: d2 = (q2 + p2) - 2*qp, plain fp32 ops, no FMA.
__device__ __forceinline__ bool in_ball(float x, float y, float z,
                                        float qx, float qy, float qz, float q2) {
    const float p2 = __fadd_rn(__fadd_rn(__fmul_rn(x, x), __fmul_rn(y, y)),
                               __fmul_rn(z, z));
    const float qp = __fadd_rn(__fadd_rn(__fmul_rn(x, qx), __fmul_rn(y, qy)),
                               __fmul_rn(z, qz));
    const float d2 = __fsub_rn(__fadd_rn(q2, p2), __fmul_rn(2.0f, qp));
    return d2 < RADIUS2;
}

// ---------------------------------------------------------------------------
// Kernel 2: ball query + group. One warp per query point (b, s).
// Scan: 128 points / iteration (4 per lane, 3 contiguous float4 loads),
//       software-pipelined prefetch of the next chunk. Early exit at 32 found.
// Gather: COALESCED — 32 lanes read one neighbor's contiguous 128B channel row,
//         transpose through a 32x33 smem tile (two 32-channel halves),
//         stores coalesced with k innermost.
// ---------------------------------------------------------------------------
#define WARPS_PER_BLOCK 4

__global__ void __launch_bounds__(128) qag_kernel(const float* __restrict__ xyz,
                                                  const float* __restrict__ new_xyz,
                                                  float* __restrict__ out) {
    __shared__ int   sidx[WARPS_PER_BLOCK][NSAMPLE];
    __shared__ float tile[WARPS_PER_BLOCK][32 * 33];  // [c][k] padded, reused per half

    const int warp = threadIdx.x >> 5;
    const int lane = threadIdx.x & 31;
    const int q    = blockIdx.x * WARPS_PER_BLOCK + warp;   // global query id
    const int b    = q / SQ;
    const int s    = q % SQ;

    const float* nq = new_xyz + ((size_t)b * SQ + s) * 3;
    const float qx = nq[0], qy = nq[1], qz = nq[2];
    const float q2 = __fadd_rn(__fadd_rn(__fmul_rn(qx, qx), __fmul_rn(qy, qy)),
                               __fmul_rn(qz, qz));

    const float* px = xyz + (size_t)b * NPTS * 3;
    const float4* v = (const float4*)px;

    // ---------------- ball query: pipelined scan, early exit -----------------
    int cnt = 0;
    const unsigned full  = 0xffffffffu;
    const unsigned below = (1u << lane) - 1u;

    // Preload chunk 0 (each lane: 4 points = 3 contiguous float4s).
    float4 A  = v[3 * lane + 0];
    float4 Bv = v[3 * lane + 1];
    float4 Cv = v[3 * lane + 2];

    for (int base = 0; base < NPTS; base += 128) {
        // Prefetch next chunk (wraps to 0 on last iter; branch-free, harmless).
        const int nb = (base + 128) & (NPTS - 1);
        const float4* nv = (const float4*)(px + (size_t)nb * 3);
        const float4 nA = nv[3 * lane + 0];
        const float4 nB = nv[3 * lane + 1];
        const float4 nC = nv[3 * lane + 2];

        // points: P0=(A.x,A.y,A.z) P1=(A.w,Bv.x,Bv.y) P2=(Bv.z,Bv.w,Cv.x) P3=(Cv.y,Cv.z,Cv.w)
        unsigned m4 = 0;
        m4 |= (unsigned)in_ball(A.x,  A.y,  A.z,  qx, qy, qz, q2) << 0;
        m4 |= (unsigned)in_ball(A.w,  Bv.x, Bv.y, qx, qy, qz, q2) << 1;
        m4 |= (unsigned)in_ball(Bv.z, Bv.w, Cv.x, qx, qy, qz, q2) << 2;
        m4 |= (unsigned)in_ball(Cv.y, Cv.z, Cv.w, qx, qy, qz, q2) << 3;

        const unsigned b0 = __ballot_sync(full, m4 & 1u);
        const unsigned b1 = __ballot_sync(full, m4 & 2u);
        const unsigned b2 = __ballot_sync(full, m4 & 4u);
        const unsigned b3 = __ballot_sync(full, m4 & 8u);

        if (m4) {
            // in-ball points of lower lanes all have smaller point index
            const int pre = __popc(b0 & below) + __popc(b1 & below)
                          + __popc(b2 & below) + __popc(b3 & below);
#pragma unroll
            for (int j = 0; j < 4; j++) {
                if ((m4 >> j) & 1u) {
                    const int slot = cnt + pre + __popc(m4 & ((1u << j) - 1u));
                    if (slot < NSAMPLE) sidx[warp][slot] = base + 4 * lane + j;
                }
            }
        }
        cnt += __popc(b0) + __popc(b1) + __popc(b2) + __popc(b3);  // warp-uniform
        if (cnt >= NSAMPLE) break;                                 // uniform branch

        A = nA; Bv = nB; Cv = nC;
    }
    __syncwarp();

    // Pad with first index; all-zeros if no neighbor at all (matches reference).
    int myidx;
    if (cnt == 0) {
        myidx = 0;
    } else {
        const int c = cnt < NSAMPLE ? cnt : NSAMPLE;
        myidx = sidx[warp][lane < c ? lane : 0];
    }

    // ---------------- grouped_xyz: lane k handles neighbor k -----------------
    const size_t chs = (size_t)SQ * NSAMPLE;
    {
        const float x = px[myidx * 3 + 0];
        const float y = px[myidx * 3 + 1];
        const float z = px[myidx * 3 + 2];
        const size_t obase = ((size_t)b * CH_OUT) * chs + (size_t)s * NSAMPLE + lane;
        out[obase + 0 * chs] = x - qx;
        out[obase + 1 * chs] = y - qy;
        out[obase + 2 * chs] = z - qz;
    }

    // ---------------- grouped features: two 32-channel halves via smem tile --
    {
        float* t = tile[warp];
        const float* ft = g_featT + (size_t)b * NPTS * CF;
#pragma unroll
        for (int half = 0; half < 2; half++) {
#pragma unroll 8
            for (int k = 0; k < NSAMPLE; k++) {
                const int idxk = __shfl_sync(full, myidx, k);
                // coalesced 128B read of 32 contiguous channels; conflict-free store
                t[lane * 33 + k] = ft[(size_t)idxk * CF + half * 32 + lane];
            }
            __syncwarp();
            const size_t fbase = ((size_t)b * CH_OUT + 3 + half * 32) * chs
                               + (size_t)s * NSAMPLE + lane;
#pragma unroll 8
            for (int c = 0; c < 32; c++) {
                out[fbase + (size_t)c * chs] = t[c * 33 + lane];  // conflict-free
            }
            __syncwarp();  // tile reused next half
        }
    }
}

// ---------------------------------------------------------------------------
// Launch
// ---------------------------------------------------------------------------
extern "C" void kernel_launch(void* const* d_in, const int* in_sizes, int n_in,
                              void* d_out, int out_size) {
    const float* xyz      = (const float*)d_in[0];  // (B, N, 3)
    const float* new_xyz  = (const float*)d_in[1];  // (B, S, 3)
    const float* features = (const float*)d_in[2];  // (B, C, N)
    float*       out      = (float*)d_out;          // (B, 67, S, 32)

    (void)in_sizes; (void)n_in; (void)out_size;

    dim3 tgrid(NPTS / 32, CF / 32, BB);
    dim3 tblock(32, 8);
    transpose_feat_kernel<<<tgrid, tblock>>>(features);

    const int nquery = BB * SQ;                       // 8192
    const int blocks = nquery / WARPS_PER_BLOCK;      // 2048
    qag_kernel<<<blocks, WARPS_PER_BLOCK * 32>>>(xyz, new_xyz, out);
}

// round 9
// speedup vs baseline: 1.5464x; 1.0402x over previous
#include <cuda_runtime.h>

// Problem constants (fixed shapes from reference setup_inputs)
#define BB      4
#define NPTS    8192
#define SQ      2048
#define CF      64
#define NSAMPLE 32
#define CH_OUT  67      // 3 (xyz) + 64 (features)
#define RADIUS2 0.04f   // 0.2^2

// Scratch
__device__ float  g_featT[(size_t)BB * NPTS * CF];  // features transposed [B][N][C]
__device__ float4 g_xyzw[(size_t)BB * NPTS];        // packed (x, y, z, |p|^2)

// ---------------------------------------------------------------------------
// Kernel 0: pack xyz + precomputed |p|^2 (exact reference op ordering).
// ---------------------------------------------------------------------------
__global__ void __launch_bounds__(256) prep_kernel(const float* __restrict__ xyz) {
    const int i = blockIdx.x * blockDim.x + threadIdx.x;   // over BB*NPTS
    const float x = xyz[i * 3 + 0];
    const float y = xyz[i * 3 + 1];
    const float z = xyz[i * 3 + 2];
    const float p2 = __fadd_rn(__fadd_rn(__fmul_rn(x, x), __fmul_rn(y, y)),
                               __fmul_rn(z, z));
    g_xyzw[i] = make_float4(x, y, z, p2);
}

// ---------------------------------------------------------------------------
// Kernel 1: transpose features (B, C, N) -> (B, N, C)
// ---------------------------------------------------------------------------
__global__ void __launch_bounds__(256) transpose_feat_kernel(const float* __restrict__ feat) {
    __shared__ float tile[32][33];
    const int b  = blockIdx.z;
    const int n0 = blockIdx.x * 32;
    const int c0 = blockIdx.y * 32;
    const float* f  = feat    + (size_t)b * CF * NPTS;
    float*       ft = g_featT + (size_t)b * NPTS * CF;

#pragma unroll
    for (int i = 0; i < 4; i++) {
        int c = c0 + threadIdx.y + i * 8;
        int n = n0 + threadIdx.x;
        tile[threadIdx.y + i * 8][threadIdx.x] = f[(size_t)c * NPTS + n];
    }
    __syncthreads();
#pragma unroll
    for (int i = 0; i < 4; i++) {
        int n = n0 + threadIdx.y + i * 8;
        int c = c0 + threadIdx.x;
        ft[(size_t)n * CF + c] = tile[threadIdx.x][threadIdx.y + i * 8];
    }
}

// Exact reference arithmetic with precomputed p2: d2 = (q2 + p2) - 2*qp.
__device__ __forceinline__ bool in_ball_p(const float4 p,
                                          float qx, float qy, float qz, float q2) {
    const float qp = __fadd_rn(__fadd_rn(__fmul_rn(p.x, qx), __fmul_rn(p.y, qy)),
                               __fmul_rn(p.z, qz));
    const float d2 = __fsub_rn(__fadd_rn(q2, p.w), __fmul_rn(2.0f, qp));
    return d2 < RADIUS2;
}

// ---------------------------------------------------------------------------
// Kernel 2: ball query + group. One warp per query point (b, s).
// Scan: 128 points / iteration in 4 stride-32 sub-chunks; each sub-chunk is one
//       coalesced float4 load (x,y,z,p2). Prefetch next chunk. Index order is
//       sub-chunk-major so slot = cnt + popc(ballot & below). Early exit /32 pts.
// Gather: coalesced 128B feature-row reads -> 32x33 smem tile -> coalesced
//         k-innermost stores (two 32-channel halves).
// ---------------------------------------------------------------------------
#define WARPS_PER_BLOCK 4

__global__ void __launch_bounds__(128) qag_kernel(const float* __restrict__ new_xyz,
                                                  float* __restrict__ out) {
    __shared__ int   sidx[WARPS_PER_BLOCK][NSAMPLE];
    __shared__ float tile[WARPS_PER_BLOCK][32 * 33];  // [c][k] padded, reused per half

    const int warp = threadIdx.x >> 5;
    const int lane = threadIdx.x & 31;
    const int q    = blockIdx.x * WARPS_PER_BLOCK + warp;   // global query id
    const int b    = q / SQ;
    const int s    = q % SQ;

    const float* nq = new_xyz + ((size_t)b * SQ + s) * 3;
    const float qx = nq[0], qy = nq[1], qz = nq[2];
    const float q2 = __fadd_rn(__fadd_rn(__fmul_rn(qx, qx), __fmul_rn(qy, qy)),
                               __fmul_rn(qz, qz));

    const float4* vw = g_xyzw + (size_t)b * NPTS;

    // ---------------- ball query: pipelined scan, early exit every 32 pts ----
    int cnt = 0;
    const unsigned full  = 0xffffffffu;
    const unsigned below = (1u << lane) - 1u;

    // Preload chunk 0: sub-chunk j -> point (j*32 + lane), coalesced.
    float4 P0 = vw[0 * 32 + lane];
    float4 P1 = vw[1 * 32 + lane];
    float4 P2 = vw[2 * 32 + lane];
    float4 P3 = vw[3 * 32 + lane];

    for (int base = 0; base < NPTS; base += 128) {
        // Prefetch next chunk (wraps on last iter; branch-free, harmless).
        const int nb = (base + 128) & (NPTS - 1);
        const float4 N0 = vw[nb + 0 * 32 + lane];
        const float4 N1 = vw[nb + 1 * 32 + lane];
        const float4 N2 = vw[nb + 2 * 32 + lane];
        const float4 N3 = vw[nb + 3 * 32 + lane];

#pragma unroll
        for (int j = 0; j < 4; j++) {
            const float4 P = (j == 0) ? P0 : (j == 1) ? P1 : (j == 2) ? P2 : P3;
            const bool in = in_ball_p(P, qx, qy, qz, q2);
            const unsigned bj = __ballot_sync(full, in);
            if (in) {
                const int slot = cnt + __popc(bj & below);
                if (slot < NSAMPLE) sidx[warp][slot] = base + j * 32 + lane;
            }
            cnt += __popc(bj);                 // warp-uniform
            if (cnt >= NSAMPLE) goto scan_done; // uniform branch
        }
        P0 = N0; P1 = N1; P2 = N2; P3 = N3;
    }
scan_done:
    __syncwarp();

    // Pad with first index; all-zeros if no neighbor at all (matches reference).
    int myidx;
    if (cnt == 0) {
        myidx = 0;
    } else {
        const int c = cnt < NSAMPLE ? cnt : NSAMPLE;
        myidx = sidx[warp][lane < c ? lane : 0];
    }

    // ---------------- grouped_xyz: lane k handles neighbor k -----------------
    const size_t chs = (size_t)SQ * NSAMPLE;
    {
        const float4 p = vw[myidx];
        const size_t obase = ((size_t)b * CH_OUT) * chs + (size_t)s * NSAMPLE + lane;
        out[obase + 0 * chs] = p.x - qx;
        out[obase + 1 * chs] = p.y - qy;
        out[obase + 2 * chs] = p.z - qz;
    }

    // ---------------- grouped features: two 32-channel halves via smem tile --
    {
        float* t = tile[warp];
        const float* ft = g_featT + (size_t)b * NPTS * CF;
#pragma unroll
        for (int half = 0; half < 2; half++) {
#pragma unroll 8
            for (int k = 0; k < NSAMPLE; k++) {
                const int idxk = __shfl_sync(full, myidx, k);
                // coalesced 128B read of 32 contiguous channels; conflict-free store
                t[lane * 33 + k] = ft[(size_t)idxk * CF + half * 32 + lane];
            }
            __syncwarp();
            const size_t fbase = ((size_t)b * CH_OUT + 3 + half * 32) * chs
                               + (size_t)s * NSAMPLE + lane;
#pragma unroll 8
            for (int c = 0; c < 32; c++) {
                out[fbase + (size_t)c * chs] = t[c * 33 + lane];  // conflict-free
            }
            __syncwarp();  // tile reused next half
        }
    }
}

// ---------------------------------------------------------------------------
// Launch
// ---------------------------------------------------------------------------
extern "C" void kernel_launch(void* const* d_in, const int* in_sizes, int n_in,
                              void* d_out, int out_size) {
    const float* xyz      = (const float*)d_in[0];  // (B, N, 3)
    const float* new_xyz  = (const float*)d_in[1];  // (B, S, 3)
    const float* features = (const float*)d_in[2];  // (B, C, N)
    float*       out      = (float*)d_out;          // (B, 67, S, 32)

    (void)in_sizes; (void)n_in; (void)out_size;

    prep_kernel<<<(BB * NPTS) / 256, 256>>>(xyz);

    dim3 tgrid(NPTS / 32, CF / 32, BB);
    dim3 tblock(32, 8);
    transpose_feat_kernel<<<tgrid, tblock>>>(features);

    const int nquery = BB * SQ;                       // 8192
    const int blocks = nquery / WARPS_PER_BLOCK;      // 2048
    qag_kernel<<<blocks, WARPS_PER_BLOCK * 32>>>(new_xyz, out);
}

// round 12
// speedup vs baseline: 1.6442x; 1.0633x over previous
#include <cuda_runtime.h>

// Problem constants (fixed shapes from reference setup_inputs)
#define BB      4
#define NPTS    8192
#define SQ      2048
#define CF      64
#define NSAMPLE 32
#define CH_OUT  67      // 3 (xyz) + 64 (features)
#define RADIUS2 0.04f   // 0.2^2

// Scratch
__device__ float  g_featT[(size_t)BB * NPTS * CF];  // features transposed [B][N][C]
__device__ float4 g_xyzw[(size_t)BB * NPTS];        // packed (x, y, z, |p|^2)

// ---------------------------------------------------------------------------
// Kernel 1 (fused): blocks [0, 2048)   -> transpose features (B,C,N)->(B,N,C)
//                   blocks [2048, 2176) -> pack (x, y, z, |p|^2)
// Both jobs run concurrently in one launch; qag depends on both.
// ---------------------------------------------------------------------------
#define TRANSPOSE_BLOCKS (NPTS / 32 * (CF / 32) * BB)   // 2048
#define PREP_BLOCKS      ((BB * NPTS) / 256)            // 128

__global__ void __launch_bounds__(256) prep_transpose_kernel(const float* __restrict__ feat,
                                                             const float* __restrict__ xyz) {
    __shared__ float tile[32][33];
    const int bid = blockIdx.x;

    if (bid < TRANSPOSE_BLOCKS) {
        // ---- transpose: recover (n-tile, c-tile, batch) from flat bid ----
        const int tx = threadIdx.x & 31;
        const int ty = threadIdx.x >> 5;          // 0..7
        const int b  = bid >> 9;                  // 512 blocks per batch
        const int rem = bid & 511;
        const int c0 = (rem >> 8) * 32;           // 0 or 32
        const int n0 = (rem & 255) * 32;

        const float* f  = feat    + (size_t)b * CF * NPTS;
        float*       ft = g_featT + (size_t)b * NPTS * CF;

#pragma unroll
        for (int i = 0; i < 4; i++) {
            int c = c0 + ty + i * 8;
            int n = n0 + tx;
            tile[ty + i * 8][tx] = f[(size_t)c * NPTS + n];
        }
        __syncthreads();
#pragma unroll
        for (int i = 0; i < 4; i++) {
            int n = n0 + ty + i * 8;
            int c = c0 + tx;
            ft[(size_t)n * CF + c] = tile[tx][ty + i * 8];
        }
    } else {
        // ---- prep: pack xyz + |p|^2 (exact reference op ordering) ----
        const int i = (bid - TRANSPOSE_BLOCKS) * 256 + threadIdx.x;  // over BB*NPTS
        const float x = xyz[i * 3 + 0];
        const float y = xyz[i * 3 + 1];
        const float z = xyz[i * 3 + 2];
        const float p2 = __fadd_rn(__fadd_rn(__fmul_rn(x, x), __fmul_rn(y, y)),
                                   __fmul_rn(z, z));
        g_xyzw[i] = make_float4(x, y, z, p2);
    }
}

// Exact reference arithmetic with precomputed p2: d2 = (q2 + p2) - 2*qp.
__device__ __forceinline__ bool in_ball_p(const float4 p,
                                          float qx, float qy, float qz, float q2) {
    const float qp = __fadd_rn(__fadd_rn(__fmul_rn(p.x, qx), __fmul_rn(p.y, qy)),
                               __fmul_rn(p.z, qz));
    const float d2 = __fsub_rn(__fadd_rn(q2, p.w), __fmul_rn(2.0f, qp));
    return d2 < RADIUS2;
}

// ---------------------------------------------------------------------------
// Kernel 2: ball query + group. One warp per query point (b, s).
// Scan: 128 points / iteration in 4 stride-32 sub-chunks (coalesced float4
//       loads), next chunk prefetched. The 4 ballots issue back-to-back
//       (independent — latencies overlap), counts combined once, one exit
//       check per 128 points. Slot order preserved via uniform prefix sums.
// Gather: coalesced 128B feature-row reads -> 32x33 smem tile -> coalesced
//         k-innermost stores (two 32-channel halves).
// ---------------------------------------------------------------------------
#define WARPS_PER_BLOCK 4

__global__ void __launch_bounds__(128) qag_kernel(const float* __restrict__ new_xyz,
                                                  float* __restrict__ out) {
    __shared__ int   sidx[WARPS_PER_BLOCK][NSAMPLE];
    __shared__ float tile[WARPS_PER_BLOCK][32 * 33];  // [c][k] padded, reused per half

    const int warp = threadIdx.x >> 5;
    const int lane = threadIdx.x & 31;
    const int q    = blockIdx.x * WARPS_PER_BLOCK + warp;   // global query id
    const int b    = q / SQ;
    const int s    = q % SQ;

    const float* nq = new_xyz + ((size_t)b * SQ + s) * 3;
    const float qx = nq[0], qy = nq[1], qz = nq[2];
    const float q2 = __fadd_rn(__fadd_rn(__fmul_rn(qx, qx), __fmul_rn(qy, qy)),
                               __fmul_rn(qz, qz));

    const float4* vw = g_xyzw + (size_t)b * NPTS;

    // ---------------- ball query: pipelined scan, batched ballots ------------
    int cnt = 0;
    const unsigned full  = 0xffffffffu;
    const unsigned below = (1u << lane) - 1u;

    // Preload chunk 0: sub-chunk j -> point (j*32 + lane), coalesced.
    float4 P0 = vw[0 * 32 + lane];
    float4 P1 = vw[1 * 32 + lane];
    float4 P2 = vw[2 * 32 + lane];
    float4 P3 = vw[3 * 32 + lane];

    for (int base = 0; base < NPTS; base += 128) {
        // Prefetch next chunk (wraps on last iter; branch-free, harmless).
        const int nb = (base + 128) & (NPTS - 1);
        const float4 N0 = vw[nb + 0 * 32 + lane];
        const float4 N1 = vw[nb + 1 * 32 + lane];
        const float4 N2 = vw[nb + 2 * 32 + lane];
        const float4 N3 = vw[nb + 3 * 32 + lane];

        const bool i0 = in_ball_p(P0, qx, qy, qz, q2);
        const bool i1 = in_ball_p(P1, qx, qy, qz, q2);
        const bool i2 = in_ball_p(P2, qx, qy, qz, q2);
        const bool i3 = in_ball_p(P3, qx, qy, qz, q2);

        // Independent ballots: issue back-to-back, latencies overlap.
        const unsigned b0 = __ballot_sync(full, i0);
        const unsigned b1 = __ballot_sync(full, i1);
        const unsigned b2 = __ballot_sync(full, i2);
        const unsigned b3 = __ballot_sync(full, i3);

        const int c0 = __popc(b0), c1 = __popc(b1), c2 = __popc(b2), c3 = __popc(b3);
        // Uniform prefix over sub-chunks (index order: sub-chunk-major).
        const int s1 = c0, s2 = c0 + c1, s3 = s2 + c2;

        if (i0) { const int sl = cnt      + __popc(b0 & below); if (sl < NSAMPLE) sidx[warp][sl] = base + 0 * 32 + lane; }
        if (i1) { const int sl = cnt + s1 + __popc(b1 & below); if (sl < NSAMPLE) sidx[warp][sl] = base + 1 * 32 + lane; }
        if (i2) { const int sl = cnt + s2 + __popc(b2 & below); if (sl < NSAMPLE) sidx[warp][sl] = base + 2 * 32 + lane; }
        if (i3) { const int sl = cnt + s3 + __popc(b3 & below); if (sl < NSAMPLE) sidx[warp][sl] = base + 3 * 32 + lane; }

        cnt += s3 + c3;                     // warp-uniform
        if (cnt >= NSAMPLE) break;          // uniform branch, once per 128 pts

        P0 = N0; P1 = N1; P2 = N2; P3 = N3;
    }
    __syncwarp();

    // Pad with first index; all-zeros if no neighbor at all (matches reference).
    int myidx;
    if (cnt == 0) {
        myidx = 0;
    } else {
        const int c = cnt < NSAMPLE ? cnt : NSAMPLE;
        myidx = sidx[warp][lane < c ? lane : 0];
    }

    // ---------------- grouped_xyz: lane k handles neighbor k -----------------
    const size_t chs = (size_t)SQ * NSAMPLE;
    {
        const float4 p = vw[myidx];
        const size_t obase = ((size_t)b * CH_OUT) * chs + (size_t)s * NSAMPLE + lane;
        out[obase + 0 * chs] = p.x - qx;
        out[obase + 1 * chs] = p.y - qy;
        out[obase + 2 * chs] = p.z - qz;
    }

    // ---------------- grouped features: two 32-channel halves via smem tile --
    {
        float* t = tile[warp];
        const float* ft = g_featT + (size_t)b * NPTS * CF;
#pragma unroll
        for (int half = 0; half < 2; half++) {
#pragma unroll 8
            for (int k = 0; k < NSAMPLE; k++) {
                const int idxk = __shfl_sync(full, myidx, k);
                // coalesced 128B read of 32 contiguous channels; conflict-free store
                t[lane * 33 + k] = ft[(size_t)idxk * CF + half * 32 + lane];
            }
            __syncwarp();
            const size_t fbase = ((size_t)b * CH_OUT + 3 + half * 32) * chs
                               + (size_t)s * NSAMPLE + lane;
#pragma unroll 8
            for (int c = 0; c < 32; c++) {
                out[fbase + (size_t)c * chs] = t[c * 33 + lane];  // conflict-free
            }
            __syncwarp();  // tile reused next half
        }
    }
}

// ---------------------------------------------------------------------------
// Launch
// ---------------------------------------------------------------------------
extern "C" void kernel_launch(void* const* d_in, const int* in_sizes, int n_in,
                              void* d_out, int out_size) {
    const float* xyz      = (const float*)d_in[0];  // (B, N, 3)
    const float* new_xyz  = (const float*)d_in[1];  // (B, S, 3)
    const float* features = (const float*)d_in[2];  // (B, C, N)
    float*       out      = (float*)d_out;          // (B, 67, S, 32)

    (void)in_sizes; (void)n_in; (void)out_size;

    // Fused prep + transpose: one launch, jobs overlap.
    prep_transpose_kernel<<<TRANSPOSE_BLOCKS + PREP_BLOCKS, 256>>>(features, xyz);

    const int nquery = BB * SQ;                       // 8192
    const int blocks = nquery / WARPS_PER_BLOCK;      // 2048
    qag_kernel<<<blocks, WARPS_PER_BLOCK * 32>>>(new_xyz, out);
}

// round 13
// speedup vs baseline: 1.7147x; 1.0428x over previous
#include <cuda_runtime.h>

// Problem constants (fixed shapes from reference setup_inputs)
#define BB      4
#define NPTS    8192
#define SQ      2048
#define CF      64
#define NSAMPLE 32
#define CH_OUT  67      // 3 (xyz) + 64 (features)
#define RADIUS2 0.04f   // 0.2^2

// Scratch
__device__ float  g_featT[(size_t)BB * NPTS * CF];  // features transposed [B][N][C]
__device__ float4 g_xyzw[(size_t)BB * NPTS];        // packed (x, y, z, |p|^2)

// ---------------------------------------------------------------------------
// Kernel 1 (fused): blocks [0, 2048)   -> transpose features (B,C,N)->(B,N,C)
//                   blocks [2048, 2176) -> pack (x, y, z, |p|^2)
// ---------------------------------------------------------------------------
#define TRANSPOSE_BLOCKS (NPTS / 32 * (CF / 32) * BB)   // 2048
#define PREP_BLOCKS      ((BB * NPTS) / 256)            // 128

__global__ void __launch_bounds__(256) prep_transpose_kernel(const float* __restrict__ feat,
                                                             const float* __restrict__ xyz) {
    __shared__ float tile[32][33];
    const int bid = blockIdx.x;

    if (bid < TRANSPOSE_BLOCKS) {
        const int tx = threadIdx.x & 31;
        const int ty = threadIdx.x >> 5;          // 0..7
        const int b  = bid >> 9;                  // 512 blocks per batch
        const int rem = bid & 511;
        const int c0 = (rem >> 8) * 32;           // 0 or 32
        const int n0 = (rem & 255) * 32;

        const float* f  = feat    + (unsigned)b * (CF * NPTS);
        float*       ft = g_featT + (unsigned)b * (NPTS * CF);

#pragma unroll
        for (int i = 0; i < 4; i++) {
            int c = c0 + ty + i * 8;
            int n = n0 + tx;
            tile[ty + i * 8][tx] = f[(unsigned)c * NPTS + n];
        }
        __syncthreads();
#pragma unroll
        for (int i = 0; i < 4; i++) {
            int n = n0 + ty + i * 8;
            int c = c0 + tx;
            ft[(unsigned)n * CF + c] = tile[tx][ty + i * 8];
        }
    } else {
        const int i = (bid - TRANSPOSE_BLOCKS) * 256 + threadIdx.x;  // over BB*NPTS
        const float x = xyz[i * 3 + 0];
        const float y = xyz[i * 3 + 1];
        const float z = xyz[i * 3 + 2];
        const float p2 = __fadd_rn(__fadd_rn(__fmul_rn(x, x), __fmul_rn(y, y)),
                                   __fmul_rn(z, z));
        g_xyzw[i] = make_float4(x, y, z, p2);
    }
}

// Exact reference arithmetic with precomputed p2: d2 = (q2 + p2) - 2*qp.
__device__ __forceinline__ bool in_ball_p(const float4 p,
                                          float qx, float qy, float qz, float q2) {
    const float qp = __fadd_rn(__fadd_rn(__fmul_rn(p.x, qx), __fmul_rn(p.y, qy)),
                               __fmul_rn(p.z, qz));
    const float d2 = __fsub_rn(__fadd_rn(q2, p.w), __fmul_rn(2.0f, qp));
    return d2 < RADIUS2;
}

// ---------------------------------------------------------------------------
// Kernel 2: ball query + group. One warp per query point (b, s).
// Scan: unrolled x2 (no double-buffer register moves), 128 points per test
//       block in 4 stride-32 sub-chunks, batched independent ballots,
//       one uniform exit check per 128 points.
// Gather: padded indices in smem; 8 iters/half of LDS idx -> LDG.128 ->
//         4 conflict-free STS into a [k][c] stride-33 tile; conflict-free
//         scalar tile reads -> coalesced k-innermost STG. 32-bit addressing.
// ---------------------------------------------------------------------------
#define WARPS_PER_BLOCK 4

// Test one 128-point chunk held in registers (P0..P3), at point base BASE.
#define TEST_CHUNK(P0_, P1_, P2_, P3_, BASE_)                                          \
    do {                                                                               \
        const bool i0 = in_ball_p(P0_, qx, qy, qz, q2);                                \
        const bool i1 = in_ball_p(P1_, qx, qy, qz, q2);                                \
        const bool i2 = in_ball_p(P2_, qx, qy, qz, q2);                                \
        const bool i3 = in_ball_p(P3_, qx, qy, qz, q2);                                \
        const unsigned b0 = __ballot_sync(full, i0);                                   \
        const unsigned b1 = __ballot_sync(full, i1);                                   \
        const unsigned b2 = __ballot_sync(full, i2);                                   \
        const unsigned b3 = __ballot_sync(full, i3);                                   \
        const int c0 = __popc(b0), c1 = __popc(b1), c2 = __popc(b2), c3 = __popc(b3);  \
        const int s1 = c0, s2 = c0 + c1, s3 = s2 + c2;                                 \
        if (i0) { const int sl = cnt      + __popc(b0 & below); if (sl < NSAMPLE) sidx[warp][sl] = (BASE_) +  0 + lane; } \
        if (i1) { const int sl = cnt + s1 + __popc(b1 & below); if (sl < NSAMPLE) sidx[warp][sl] = (BASE_) + 32 + lane; } \
        if (i2) { const int sl = cnt + s2 + __popc(b2 & below); if (sl < NSAMPLE) sidx[warp][sl] = (BASE_) + 64 + lane; } \
        if (i3) { const int sl = cnt + s3 + __popc(b3 & below); if (sl < NSAMPLE) sidx[warp][sl] = (BASE_) + 96 + lane; } \
        cnt += s3 + c3;                                                                \
    } while (0)

__global__ void __launch_bounds__(128) qag_kernel(const float* __restrict__ new_xyz,
                                                  float* __restrict__ out) {
    __shared__ int   sidx[WARPS_PER_BLOCK][NSAMPLE];
    __shared__ float tile[WARPS_PER_BLOCK][32 * 33];  // [k][c] stride-33, reused per half

    const int warp = threadIdx.x >> 5;
    const int lane = threadIdx.x & 31;
    const int q    = blockIdx.x * WARPS_PER_BLOCK + warp;   // global query id
    const int b    = q >> 11;        // / SQ
    const int s    = q & (SQ - 1);   // % SQ

    const float* nq = new_xyz + (unsigned)q * 3;
    const float qx = nq[0], qy = nq[1], qz = nq[2];
    const float q2 = __fadd_rn(__fadd_rn(__fmul_rn(qx, qx), __fmul_rn(qy, qy)),
                               __fmul_rn(qz, qz));

    const float4* vw = g_xyzw + (unsigned)b * NPTS;

    // ---------------- ball query: unrolled pipelined scan --------------------
    int cnt = 0;
    const unsigned full  = 0xffffffffu;
    const unsigned below = (1u << lane) - 1u;

    // Chunk register set A preloaded with chunk 0.
    float4 A0 = vw[ 0 + lane], A1 = vw[32 + lane],
           A2 = vw[64 + lane], A3 = vw[96 + lane];

    for (int base = 0; base < NPTS; base += 256) {
        // Prefetch chunk (base+128) into set B while testing set A.
        const unsigned n1 = (unsigned)(base + 128) & (NPTS - 1);
        const float4 B0 = vw[n1 +  0 + lane];
        const float4 B1 = vw[n1 + 32 + lane];
        const float4 B2 = vw[n1 + 64 + lane];
        const float4 B3 = vw[n1 + 96 + lane];

        TEST_CHUNK(A0, A1, A2, A3, base);
        if (cnt >= NSAMPLE) break;       // uniform

        // Prefetch chunk (base+256) directly into set A (no moves).
        const unsigned n2 = (unsigned)(base + 256) & (NPTS - 1);
        A0 = vw[n2 +  0 + lane];
        A1 = vw[n2 + 32 + lane];
        A2 = vw[n2 + 64 + lane];
        A3 = vw[n2 + 96 + lane];

        TEST_CHUNK(B0, B1, B2, B3, base + 128);
        if (cnt >= NSAMPLE) break;       // uniform
    }
    __syncwarp();

    // Pad with first index; all-zeros if no neighbor at all (matches reference).
    int myidx;
    if (cnt == 0) {
        myidx = 0;
    } else {
        const int c = cnt < NSAMPLE ? cnt : NSAMPLE;
        myidx = sidx[warp][lane < c ? lane : 0];
    }
    __syncwarp();
    sidx[warp][lane] = myidx;           // padded index table for the gather
    __syncwarp();

    // ---------------- grouped_xyz: lane k handles neighbor k -----------------
    const unsigned chs = SQ * NSAMPLE;  // 65536
    {
        const float4 p = vw[myidx];
        float* o = out + ((unsigned)b * CH_OUT) * chs + (unsigned)s * NSAMPLE + lane;
        o[0 * chs] = p.x - qx;
        o[1 * chs] = p.y - qy;
        o[2 * chs] = p.z - qz;
    }

    // ---------------- grouped features: two 32-channel halves ----------------
    {
        float* t = tile[warp];
        const float* ft = g_featT + (unsigned)b * (NPTS * CF);
        const int krow = lane >> 3;         // 0..3
        const int c4   = (lane & 7) * 4;    // 0,4,...,28
#pragma unroll
        for (int half = 0; half < 2; half++) {
#pragma unroll
            for (int i = 0; i < 8; i++) {
                const int k    = i * 4 + krow;
                const int idxk = sidx[warp][k];
                const float4 v = *(const float4*)(ft + (unsigned)idxk * CF + half * 32 + c4);
                // conflict-free: bank = (k + c4 + j) & 31, distinct across lanes
                float* tk = t + k * 33 + c4;
                tk[0] = v.x; tk[1] = v.y; tk[2] = v.z; tk[3] = v.w;
            }
            __syncwarp();
            // conflict-free reads (bank = (lane + c) & 31), coalesced stores
            float* o = out + ((unsigned)b * CH_OUT + 3 + half * 32) * chs
                           + (unsigned)s * NSAMPLE + lane;
            const float* tr = t + lane * 33;
#pragma unroll 8
            for (int c = 0; c < 32; c++) {
                *o = tr[c];
                o += chs;
            }
            __syncwarp();  // tile reused next half
        }
    }
}

// ---------------------------------------------------------------------------
// Launch
// ---------------------------------------------------------------------------
extern "C" void kernel_launch(void* const* d_in, const int* in_sizes, int n_in,
                              void* d_out, int out_size) {
    const float* xyz      = (const float*)d_in[0];  // (B, N, 3)
    const float* new_xyz  = (const float*)d_in[1];  // (B, S, 3)
    const float* features = (const float*)d_in[2];  // (B, C, N)
    float*       out      = (float*)d_out;          // (B, 67, S, 32)

    (void)in_sizes; (void)n_in; (void)out_size;

    prep_transpose_kernel<<<TRANSPOSE_BLOCKS + PREP_BLOCKS, 256>>>(features, xyz);

    const int nquery = BB * SQ;                       // 8192
    const int blocks = nquery / WARPS_PER_BLOCK;      // 2048
    qag_kernel<<<blocks, WARPS_PER_BLOCK * 32>>>(new_xyz, out);
}

// round 15
// speedup vs baseline: 1.7677x; 1.0309x over previous
#include <cuda_runtime.h>

// Problem constants (fixed shapes from reference setup_inputs)
#define BB      4
#define NPTS    8192
#define SQ      2048
#define CF      64
#define NSAMPLE 32
#define CH_OUT  67      // 3 (xyz) + 64 (features)
#define RADIUS2 0.04f   // 0.2^2

// Scratch
__device__ float  g_featT[(size_t)BB * NPTS * CF];  // features transposed [B][N][C]
__device__ float4 g_xyzw[(size_t)BB * NPTS];        // packed (x, y, z, |p|^2)

// ---------------------------------------------------------------------------
// Kernel 1 (fused): blocks [0, 2048)   -> transpose features (B,C,N)->(B,N,C)
//                   blocks [2048, 2176) -> pack (x, y, z, |p|^2)
// ---------------------------------------------------------------------------
#define TRANSPOSE_BLOCKS (NPTS / 32 * (CF / 32) * BB)   // 2048
#define PREP_BLOCKS      ((BB * NPTS) / 256)            // 128

__global__ void __launch_bounds__(256) prep_transpose_kernel(const float* __restrict__ feat,
                                                             const float* __restrict__ xyz) {
    __shared__ float tile[32][33];
    const int bid = blockIdx.x;

    if (bid < TRANSPOSE_BLOCKS) {
        const int tx = threadIdx.x & 31;
        const int ty = threadIdx.x >> 5;          // 0..7
        const int b  = bid >> 9;                  // 512 blocks per batch
        const int rem = bid & 511;
        const int c0 = (rem >> 8) * 32;           // 0 or 32
        const int n0 = (rem & 255) * 32;

        const float* f  = feat    + (unsigned)b * (CF * NPTS);
        float*       ft = g_featT + (unsigned)b * (NPTS * CF);

#pragma unroll
        for (int i = 0; i < 4; i++) {
            int c = c0 + ty + i * 8;
            int n = n0 + tx;
            tile[ty + i * 8][tx] = f[(unsigned)c * NPTS + n];
        }
        __syncthreads();
#pragma unroll
        for (int i = 0; i < 4; i++) {
            int n = n0 + ty + i * 8;
            int c = c0 + tx;
            ft[(unsigned)n * CF + c] = tile[tx][ty + i * 8];
        }
    } else {
        const int i = (bid - TRANSPOSE_BLOCKS) * 256 + threadIdx.x;  // over BB*NPTS
        const float x = xyz[i * 3 + 0];
        const float y = xyz[i * 3 + 1];
        const float z = xyz[i * 3 + 2];
        const float p2 = __fadd_rn(__fadd_rn(__fmul_rn(x, x), __fmul_rn(y, y)),
                                   __fmul_rn(z, z));
        g_xyzw[i] = make_float4(x, y, z, p2);
    }
}

// Exact reference arithmetic with precomputed p2: d2 = (q2 + p2) - 2*qp.
__device__ __forceinline__ bool in_ball_p(const float4 p,
                                          float qx, float qy, float qz, float q2) {
    const float qp = __fadd_rn(__fadd_rn(__fmul_rn(p.x, qx), __fmul_rn(p.y, qy)),
                               __fmul_rn(p.z, qz));
    const float d2 = __fsub_rn(__fadd_rn(q2, p.w), __fmul_rn(2.0f, qp));
    return d2 < RADIUS2;
}

// ---------------------------------------------------------------------------
// Kernel 2: ball query + group. ONE WARP PER BLOCK, one query per block.
// 8192 blocks @ 32-thread blocks -> stragglers don't pin sibling warps and
// finished blocks are backfilled by the scheduler.
// Scan: unrolled x2 pipelined, 4 stride-32 sub-chunks per 128-pt test,
//       batched ballots, selection skipped on zero-hit chunks.
// Gather: [c][k] stride-33 smem tile. STS phase: bank=(c+k)&31, c4+krow
//       bijective over lanes -> conflict-free. Read phase: 4 scalar LDS
//       (bank=(c+kg4+m)&31, cr+kg4 bijective -> conflict-free) packed into
//       one aligned STG.128 (coalesced 128B rows). 32-bit addressing.
// ---------------------------------------------------------------------------

// Test one 128-point chunk held in registers (P0..P3), at point base BASE.
#define TEST_CHUNK(P0_, P1_, P2_, P3_, BASE_)                                          \
    do {                                                                               \
        const bool i0 = in_ball_p(P0_, qx, qy, qz, q2);                                \
        const bool i1 = in_ball_p(P1_, qx, qy, qz, q2);                                \
        const bool i2 = in_ball_p(P2_, qx, qy, qz, q2);                                \
        const bool i3 = in_ball_p(P3_, qx, qy, qz, q2);                                \
        const unsigned b0 = __ballot_sync(full, i0);                                   \
        const unsigned b1 = __ballot_sync(full, i1);                                   \
        const unsigned b2 = __ballot_sync(full, i2);                                   \
        const unsigned b3 = __ballot_sync(full, i3);                                   \
        if (b0 | b1 | b2 | b3) {  /* warp-uniform: skip selection on no-hit chunks */  \
            const int c0 = __popc(b0), c1 = __popc(b1), c2 = __popc(b2);               \
            const int s1 = c0, s2 = c0 + c1, s3 = s2 + c2;                             \
            if (i0) { const int sl = cnt      + __popc(b0 & below); if (sl < NSAMPLE) sidx[sl] = (BASE_) +  0 + lane; } \
            if (i1) { const int sl = cnt + s1 + __popc(b1 & below); if (sl < NSAMPLE) sidx[sl] = (BASE_) + 32 + lane; } \
            if (i2) { const int sl = cnt + s2 + __popc(b2 & below); if (sl < NSAMPLE) sidx[sl] = (BASE_) + 64 + lane; } \
            if (i3) { const int sl = cnt + s3 + __popc(b3 & below); if (sl < NSAMPLE) sidx[sl] = (BASE_) + 96 + lane; } \
            cnt += s3 + __popc(b3);   /* total hits this chunk: c0+c1+c2+c3 */         \
        }                                                                              \
    } while (0)

__global__ void __launch_bounds__(32) qag_kernel(const float* __restrict__ new_xyz,
                                                 float* __restrict__ out) {
    __shared__ int   sidx[NSAMPLE];
    __shared__ float tile[32 * 33];   // [c][k] stride-33, reused per half

    const int lane = threadIdx.x;
    const int q    = blockIdx.x;     // one query per block
    const int b    = q >> 11;        // / SQ
    const int s    = q & (SQ - 1);   // % SQ

    const float* nq = new_xyz + (unsigned)q * 3;
    const float qx = nq[0], qy = nq[1], qz = nq[2];
    const float q2 = __fadd_rn(__fadd_rn(__fmul_rn(qx, qx), __fmul_rn(qy, qy)),
                               __fmul_rn(qz, qz));

    const float4* vw = g_xyzw + (unsigned)b * NPTS;

    // ---------------- ball query: unrolled pipelined scan --------------------
    int cnt = 0;
    const unsigned full  = 0xffffffffu;
    const unsigned below = (1u << lane) - 1u;

    // Chunk register set A preloaded with chunk 0.
    float4 A0 = vw[ 0 + lane], A1 = vw[32 + lane],
           A2 = vw[64 + lane], A3 = vw[96 + lane];

    for (int base = 0; base < NPTS; base += 256) {
        // Prefetch chunk (base+128) into set B while testing set A.
        const unsigned n1 = (unsigned)(base + 128) & (NPTS - 1);
        const float4 B0 = vw[n1 +  0 + lane];
        const float4 B1 = vw[n1 + 32 + lane];
        const float4 B2 = vw[n1 + 64 + lane];
        const float4 B3 = vw[n1 + 96 + lane];

        TEST_CHUNK(A0, A1, A2, A3, base);
        if (cnt >= NSAMPLE) break;       // uniform

        // Prefetch chunk (base+256) directly into set A (no moves).
        const unsigned n2 = (unsigned)(base + 256) & (NPTS - 1);
        A0 = vw[n2 +  0 + lane];
        A1 = vw[n2 + 32 + lane];
        A2 = vw[n2 + 64 + lane];
        A3 = vw[n2 + 96 + lane];

        TEST_CHUNK(B0, B1, B2, B3, base + 128);
        if (cnt >= NSAMPLE) break;       // uniform
    }
    __syncwarp();

    // Pad with first index; all-zeros if no neighbor at all (matches reference).
    int myidx;
    if (cnt == 0) {
        myidx = 0;
    } else {
        const int c = cnt < NSAMPLE ? cnt : NSAMPLE;
        myidx = sidx[lane < c ? lane : 0];
    }
    __syncwarp();
    sidx[lane] = myidx;                 // padded index table for the gather
    __syncwarp();

    // ---------------- grouped_xyz: lane k handles neighbor k -----------------
    const unsigned chs = SQ * NSAMPLE;  // 65536
    {
        const float4 p = vw[myidx];
        float* o = out + ((unsigned)b * CH_OUT) * chs + (unsigned)s * NSAMPLE + lane;
        o[0 * chs] = p.x - qx;
        o[1 * chs] = p.y - qy;
        o[2 * chs] = p.z - qz;
    }

    // ---------------- grouped features: two 32-channel halves ----------------
    {
        const float* ft = g_featT + (unsigned)b * (NPTS * CF);
        const int krow = lane >> 3;         // 0..3  (store phase)
        const int c4   = (lane & 7) * 4;    // 0,4,...,28
        const int cr   = lane >> 3;         // 0..3  (read phase: channel offset)
        const int kg4  = (lane & 7) * 4;    // 0,4,...,28 (read phase: k base)
#pragma unroll
        for (int half = 0; half < 2; half++) {
            // Store: LDG.128 of 4 channels for neighbor k -> 4 scalar STS.
            // bank(tile[(c4+j)*33 + k]) = (c4 + j + k) & 31; c4 + krow is a
            // bijection onto 0..31 -> conflict-free for each j.
#pragma unroll
            for (int i = 0; i < 8; i++) {
                const int k    = i * 4 + krow;
                const int idxk = sidx[k];
                const float4 v = *(const float4*)(ft + (unsigned)idxk * CF + half * 32 + c4);
                tile[(c4 + 0) * 33 + k] = v.x;
                tile[(c4 + 1) * 33 + k] = v.y;
                tile[(c4 + 2) * 33 + k] = v.z;
                tile[(c4 + 3) * 33 + k] = v.w;
            }
            __syncwarp();
            // Read: 4 scalar LDS (bank = (c + kg4 + m) & 31; cr + kg4 bijective
            // -> conflict-free per m), pack, one aligned coalesced STG.128.
            float* obase = out + ((unsigned)b * CH_OUT + 3 + half * 32) * chs
                               + (unsigned)s * NSAMPLE;
#pragma unroll
            for (int i = 0; i < 8; i++) {
                const int c = i * 4 + cr;
                const float* tr = tile + c * 33 + kg4;
                const float4 v = make_float4(tr[0], tr[1], tr[2], tr[3]);
                *(float4*)(obase + (unsigned)c * chs + kg4) = v;
            }
            __syncwarp();  // tile reused next half
        }
    }
}

// ---------------------------------------------------------------------------
// Launch
// ---------------------------------------------------------------------------
extern "C" void kernel_launch(void* const* d_in, const int* in_sizes, int n_in,
                              void* d_out, int out_size) {
    const float* xyz      = (const float*)d_in[0];  // (B, N, 3)
    const float* new_xyz  = (const float*)d_in[1];  // (B, S, 3)
    const float* features = (const float*)d_in[2];  // (B, C, N)
    float*       out      = (float*)d_out;          // (B, 67, S, 32)

    (void)in_sizes; (void)n_in; (void)out_size;

    prep_transpose_kernel<<<TRANSPOSE_BLOCKS + PREP_BLOCKS, 256>>>(features, xyz);

    const int nquery = BB * SQ;                       // 8192
    qag_kernel<<<nquery, 32>>>(new_xyz, out);
}